// round 14
// baseline (speedup 1.0000x reference)
#include <cuda_runtime.h>
#include <cuda_fp16.h>
#include <cstdint>

// ---------------------------------------------------------------- constants
#define NPTS    16384
#define KCODES  8192
#define DDIM    128
#define HWSZ    1024
#define MTILE   128                 // points per item
#define CTILE   128                 // codes per code-tile (per stage)
#define NSPLIT  16                  // K-splits (512 codes each)
#define KPER    (KCODES / NSPLIT)   // 512
#define NCT     (KPER / CTILE)      // 4
#define NSTAGES (NCT * 2)           // 8 (2 k-chunks per code-tile)
#define NITEMS  (NSPLIT * (NPTS / MTILE))  // 2048
#define ZSTRIDE 136                 // halves per zs row (128 + 8 pad)
#define BSTRIDE 72                  // halves per B row (64 + 8 pad)
#define BUFB    (CTILE * BSTRIDE * 2)     // 18432 B
#define NBUF    3

// Output layout (concatenated float32 outputs)
#define O_ZQ  0
#define O_IDX 2097152
#define O_CB  2113536
#define O_CNT 3162112
#define O_WT  3170304

// ---------------------------------------------------------------- scratch
__device__ float  g_cnorm[KCODES];
__device__ float  g_cnh[KCODES];                    // (cnorm - 256)/2
__device__ __half g_bext[2u * KCODES * 64];         // [chunk(hi0,hi1)][code][64]
__device__ __half g_zext[NPTS * DDIM];              // fp16(z) rows (row-major in n)
__device__ float  g_zf[NPTS * DDIM];                // fp32 z rows
__device__ float  g_pv[NSPLIT * NPTS];              // per-split min f-value
// NOTE: plain `char` is UNSIGNED on the aarch64 toolchain — must be signed char.
__device__ __align__(16) signed char g_q8[(size_t)NPTS * KCODES];  // s8 f=(dist-256)/2
__device__ int    g_idx[NPTS];
__device__ float  g_counts[KCODES];
__device__ float  g_dw[KCODES * DDIM];

// ---------------------------------------------------------------- helpers
__device__ __forceinline__ uint32_t smem_u32(const void* p) {
    uint32_t a;
    asm("{ .reg .u64 t; cvta.to.shared.u64 t, %1; cvt.u32.u64 %0, t; }" : "=r"(a) : "l"(p));
    return a;
}
__device__ __forceinline__ void cp_async16(uint32_t dst, const void* src) {
    asm volatile("cp.async.cg.shared.global [%0], [%1], 16;" :: "r"(dst), "l"(src) : "memory");
}
#define CP_COMMIT() asm volatile("cp.async.commit_group;" ::: "memory")
#define CP_WAIT1()  asm volatile("cp.async.wait_group 1;" ::: "memory")
#define CP_WAIT0()  asm volatile("cp.async.wait_group 0;" ::: "memory")

#define LDSM4(r0, r1, r2, r3, a)                                              \
    asm volatile("ldmatrix.sync.aligned.m8n8.x4.shared.b16 {%0,%1,%2,%3}, [%4];" \
                 : "=r"(r0), "=r"(r1), "=r"(r2), "=r"(r3) : "r"(a))

#define MMA16816(c, a0, a1, a2, a3, b0, b1)                                  \
    asm volatile("mma.sync.aligned.m16n8k16.row.col.f32.f16.f16.f32 "        \
                 "{%0,%1,%2,%3}, {%4,%5,%6,%7}, {%8,%9}, {%0,%1,%2,%3};"     \
                 : "+f"((c)[0]), "+f"((c)[1]), "+f"((c)[2]), "+f"((c)[3])    \
                 : "r"(a0), "r"(a1), "r"(a2), "r"(a3), "r"(b0), "r"(b1))

__device__ __forceinline__ int sx8(uint32_t u, int byi) {   // signed byte extract
    return (int)(signed char)((u >> (byi * 8)) & 0xffu);
}
__device__ __forceinline__ int cvt_s8_sat(float f) {        // fused round+saturate
    int q;
    asm("cvt.rni.sat.s8.f32 %0, %1;" : "=r"(q) : "f"(f));
    return q;
}

// ---------------------------------------------------------------- prep: codebook
__global__ void prep_cb_kernel(const float* __restrict__ cb) {
    int k = blockIdx.x, t = threadIdx.x;
    float v = cb[k * DDIM + t];
    g_dw[k * DDIM + t] = 0.0f;

    int half_ = t >> 6, pos = t & 63;
    g_bext[(size_t)half_ * (KCODES * 64) + (size_t)k * 64 + pos] = __float2half_rn(v);

    float sq = v * v;
    #pragma unroll
    for (int o = 16; o > 0; o >>= 1) sq += __shfl_down_sync(0xffffffffu, sq, o);
    __shared__ float red[4];
    if ((t & 31) == 0) red[t >> 5] = sq;
    __syncthreads();
    if (t == 0) {
        float cn = red[0] + red[1] + red[2] + red[3];
        g_cnorm[k] = cn;
        g_cnh[k] = (cn - 256.0f) * 0.5f;
        g_counts[k] = 0.0f;
    }
}

// ---------------------------------------------------------------- prep: z side
__global__ void prep_z_kernel(const float* __restrict__ z) {
    __shared__ float zsm[32 * 129];
    const int tid = threadIdx.x;
    const int n0 = blockIdx.x * 32;
    const int b = n0 >> 10, hw0 = n0 & (HWSZ - 1);
    const float* zb = z + (size_t)b * DDIM * HWSZ + hw0;
    for (int i = tid; i < 32 * DDIM; i += 256) {
        int d = i >> 5, p = i & 31;
        zsm[p * 129 + d] = zb[(size_t)d * HWSZ + p];
    }
    __syncthreads();
    uint32_t* oh = reinterpret_cast<uint32_t*>(g_zext + (size_t)n0 * DDIM);
    for (int i = tid; i < 32 * 64; i += 256) {
        int p = i >> 6, c = i & 63;
        __half2 hh = __halves2half2(__float2half_rn(zsm[p * 129 + 2 * c]),
                                    __float2half_rn(zsm[p * 129 + 2 * c + 1]));
        oh[p * 64 + c] = *reinterpret_cast<uint32_t*>(&hh);
    }
    for (int i = tid; i < 32 * DDIM; i += 256) {
        int p = i >> 7, d = i & 127;
        g_zf[(size_t)(n0 + p) * DDIM + d] = zsm[p * 129 + d];
    }
}

// ---------------------------------------------------------------- pass1: approx dist GEMM (s8) + per-split min
// grid = 2048 items, block = 256 (8 warps: 4M x 2N), warp tile 32x64, 2 CTAs/SM.
__global__ void __launch_bounds__(256, 2) dist_kernel() {
    extern __shared__ char smem[];
    char* bbase = smem + MTILE * ZSTRIDE * 2;

    const int tid = threadIdx.x;
    const int lane = tid & 31, wid = tid >> 5;
    const int wm = wid & 3;        // 4 M blocks of 32
    const int wn = wid >> 2;       // 2 N blocks of 64

    const int item = blockIdx.x;
    const int ksplit = item >> 7;          // 0..15
    const int tile = item & 127;
    const int kbeg = ksplit * KPER;
    const int pbase = tile * MTILE;

    const uint32_t zs32 = smem_u32(smem);
    const uint32_t bb32 = smem_u32(bbase);

    // z tile (group 0): 128 rows x 256B into padded 272B rows
    {
        const char* zsrc = (const char*)(g_zext + (size_t)tile * MTILE * DDIM);
        for (int j = tid; j < 2048; j += 256) {
            int row = j >> 4, c16 = j & 15;
            cp_async16(zs32 + (uint32_t)row * 272u + (uint32_t)c16 * 16u,
                       zsrc + (size_t)row * 256 + (size_t)c16 * 16);
        }
        CP_COMMIT();
    }

    const uint32_t za0 = zs32 + 2u * ((wm * 32 + (lane & 15)) * ZSTRIDE + (lane >> 4) * 8);
    const uint32_t bb0 = 2u * ((wn * 64 + (lane & 15)) * BSTRIDE + (lane >> 4) * 8);

    auto issue = [&](int s) {
        int ct = s >> 1, c = s & 1;
        const char* src = (const char*)(g_bext +
            ((size_t)c * KCODES + (size_t)(kbeg + ct * CTILE)) * 64);
        uint32_t dst = bb32 + (uint32_t)(s % NBUF) * BUFB;
        #pragma unroll
        for (int i = 0; i < 4; i++) {
            int idx = tid + i * 256;          // 0..1023 16B chunks (128 rows x 8)
            cp_async16(dst + (uint32_t)(idx >> 3) * 144u + (uint32_t)(idx & 7) * 16u,
                       src + (size_t)idx * 16);
        }
        CP_COMMIT();
    };

    float acc[2][8][4];
    float minv[4] = {3.402823466e38f, 3.402823466e38f, 3.402823466e38f, 3.402823466e38f};
    issue(0);
    issue(1);

    for (int s = 0; s < NSTAGES; s++) {
        const int ct = s >> 1, c = s & 1;
        if (s + 1 < NSTAGES) CP_WAIT1(); else CP_WAIT0();
        __syncthreads();
        if (s + 2 < NSTAGES) issue(s + 2);

        if (c == 0) {
            #pragma unroll
            for (int mt = 0; mt < 2; mt++)
                #pragma unroll
                for (int nt = 0; nt < 8; nt++)
                    #pragma unroll
                    for (int r = 0; r < 4; r++) acc[mt][nt][r] = 0.0f;
        }

        const uint32_t za = za0 + (uint32_t)c * 128u;   // chunk offset: c*64 halves
        const uint32_t bbuf = bb32 + (uint32_t)(s % NBUF) * BUFB + bb0;

        #pragma unroll
        for (int ks = 0; ks < 4; ks++) {
            uint32_t a[2][4];
            #pragma unroll
            for (int mt = 0; mt < 2; mt++)
                LDSM4(a[mt][0], a[mt][1], a[mt][2], a[mt][3],
                      za + (uint32_t)mt * (16u * ZSTRIDE * 2u) + (uint32_t)ks * 32u);
            uint32_t bf[4][4];
            #pragma unroll
            for (int np = 0; np < 4; np++)
                LDSM4(bf[np][0], bf[np][1], bf[np][2], bf[np][3],
                      bbuf + (uint32_t)np * (16u * BSTRIDE * 2u) + (uint32_t)ks * 32u);
            #pragma unroll
            for (int np = 0; np < 4; np++) {
                #pragma unroll
                for (int mt = 0; mt < 2; mt++)
                    MMA16816(acc[mt][2 * np], a[mt][0], a[mt][1], a[mt][2], a[mt][3],
                             bf[np][0], bf[np][2]);
                #pragma unroll
                for (int mt = 0; mt < 2; mt++)
                    MMA16816(acc[mt][2 * np + 1], a[mt][0], a[mt][1], a[mt][2], a[mt][3],
                             bf[np][1], bf[np][3]);
            }
        }

        if (c == 1) {
            // f = (dist-256)/2 = cnh - acc; q = sat_s8(round(f)); track running min(f).
            // Byte-position contract unchanged: pos = (lane&3)*16 + nt*2 + b within
            // each 64-code group <-> code = (lane&3)*2 + nt*8 + b.
            const int kk0 = kbeg + ct * CTILE + wn * 64 + (lane & 3) * 2;
            float2 ch[8];
            #pragma unroll
            for (int nt = 0; nt < 8; nt++)
                ch[nt] = __ldg(reinterpret_cast<const float2*>(g_cnh + kk0 + nt * 8));
            const int pcol = kbeg + ct * CTILE + wn * 64 + (lane & 3) * 16;   // bytes
            #pragma unroll
            for (int mt = 0; mt < 2; mt++) {
                #pragma unroll
                for (int hf = 0; hf < 2; hf++) {
                    const int row = pbase + wm * 32 + mt * 16 + (lane >> 2) + hf * 8;
                    const int rr = mt * 2 + hf;
                    uint32_t pq[8];
                    #pragma unroll
                    for (int nt = 0; nt < 8; nt++) {
                        float f0 = ch[nt].x - acc[mt][nt][hf * 2];
                        float f1 = ch[nt].y - acc[mt][nt][hf * 2 + 1];
                        minv[rr] = fminf(minv[rr], fminf(f0, f1));
                        pq[nt] = __byte_perm((uint32_t)cvt_s8_sat(f0),
                                             (uint32_t)cvt_s8_sat(f1), 0x0040);
                    }
                    uint32_t r32[4];
                    #pragma unroll
                    for (int p2 = 0; p2 < 4; p2++)
                        r32[p2] = __byte_perm(pq[2 * p2], pq[2 * p2 + 1], 0x5410);
                    *reinterpret_cast<int4*>(g_q8 + (size_t)row * KCODES + pcol) =
                        make_int4((int)r32[0], (int)r32[1], (int)r32[2], (int)r32[3]);
                }
            }
        }
    }

    // per-item reduce of row minima -> g_pv (value only; threshold seed)
    __syncthreads();
    float* rv = (float*)smem;                 // 128 rows x 8 slots
    const int slot = wn * 4 + (lane & 3);
    #pragma unroll
    for (int mt = 0; mt < 2; mt++)
        #pragma unroll
        for (int hf = 0; hf < 2; hf++) {
            int rloc = wm * 32 + mt * 16 + hf * 8 + (lane >> 2);
            rv[rloc * 8 + slot] = minv[mt * 2 + hf];
        }
    __syncthreads();
    if (tid < MTILE) {
        float bmin = rv[tid * 8];
        #pragma unroll
        for (int s2 = 1; s2 < 8; s2++) bmin = fminf(bmin, rv[tid * 8 + s2]);
        g_pv[ksplit * NPTS + pbase + tid] = bmin;
    }
}

// ---------------------------------------------------------------- scan v2: single pass + exact repair + EMA
__global__ void __launch_bounds__(128) scan_kernel(const float* __restrict__ cb,
                                                   float* __restrict__ out) {
    __shared__ float zrow[DDIM];
    __shared__ int   candk[128];
    __shared__ float cdist[128];
    __shared__ float sv[NSPLIT];
    __shared__ int   ccnt, covf, bidx_s, Tsh;

    const int n = blockIdx.x, t = threadIdx.x;
    const int lane = t & 31, w = t >> 5;

    zrow[t] = g_zf[(size_t)n * DDIM + t];
    if (t < NSPLIT) sv[t] = g_pv[t * NPTS + n];
    if (t == 0) { ccnt = 0; covf = 0; }

    // 8192 bytes per row = 512 int4; 128 threads x 4 int4 (loads overlap T calc)
    const int4* qrow = reinterpret_cast<const int4*>(g_q8 + (size_t)n * KCODES);
    int4 v[4];
    #pragma unroll
    for (int i = 0; i < 4; i++) v[i] = qrow[t + i * 128];

    __syncthreads();
    if (t == 0) {
        float fb = sv[0];
        #pragma unroll
        for (int s = 1; s < NSPLIT; s++) fb = fminf(fb, sv[s]);
        // window: 0.5 (s8 round) + 2x fp16 GEMM err (<0.25 f-units total) + margin
        Tsh = (int)floorf(fb) + 3;
    }
    __syncthreads();
    const int T = Tsh;

    #pragma unroll
    for (int i = 0; i < 4; i++) {
        const int pb = (t + i * 128) * 16;
        const uint32_t uu[4] = { (uint32_t)v[i].x, (uint32_t)v[i].y,
                                 (uint32_t)v[i].z, (uint32_t)v[i].w };
        #pragma unroll
        for (int j = 0; j < 4; j++) {
            #pragma unroll
            for (int byi = 0; byi < 4; byi++) {
                int q = sx8(uu[j], byi);
                if (q <= T) {
                    int pos = pb + j * 4 + byi;
                    int k = (pos & ~63) | (((pos >> 1) & 7) << 3) |
                            (((pos >> 4) & 3) << 1) | (pos & 1);
                    int slot = atomicAdd(&ccnt, 1);
                    if (slot < 128) candk[slot] = k; else covf = 1;
                }
            }
        }
    }
    __syncthreads();

    const int cnt = min(ccnt, 128);
    if (!covf && cnt > 0) {
        const float4* z4p = reinterpret_cast<const float4*>(zrow);
        for (int s = w; s < cnt; s += 4) {
            const int k = candk[s];
            const float4 c4 = __ldg(reinterpret_cast<const float4*>(cb + (size_t)k * DDIM) + lane);
            const float4 z4 = z4p[lane];
            float d = c4.x * z4.x + c4.y * z4.y + c4.z * z4.z + c4.w * z4.w;
            #pragma unroll
            for (int off = 16; off > 0; off >>= 1) d += __shfl_xor_sync(0xffffffffu, d, off);
            if (lane == 0) cdist[s] = __ldg(g_cnorm + k) - 2.0f * d;
        }
        __syncthreads();
        if (t == 0) {
            float bv = cdist[0]; int bi = candk[0];
            for (int s = 1; s < cnt; s++) {
                float dv = cdist[s]; int kv = candk[s];
                if (dv < bv || (dv == bv && kv < bi)) { bv = dv; bi = kv; }
            }
            bidx_s = bi;
        }
    } else {
        // fallback: full exact scan (defensive; statistically unreachable)
        float bv = 3.402823466e38f; int bi = 0x7fffffff;
        for (int k = t; k < KCODES; k += 128) {
            float d = 0.0f;
            #pragma unroll 8
            for (int dd = 0; dd < DDIM; dd++) d += zrow[dd] * __ldg(cb + (size_t)k * DDIM + dd);
            float dist = __ldg(g_cnorm + k) - 2.0f * d;
            if (dist < bv || (dist == bv && k < bi)) { bv = dist; bi = k; }
        }
        #pragma unroll
        for (int off = 16; off > 0; off >>= 1) {
            float ov = __shfl_xor_sync(0xffffffffu, bv, off);
            int   oi = __shfl_xor_sync(0xffffffffu, bi, off);
            if (ov < bv || (ov == bv && oi < bi)) { bv = ov; bi = oi; }
        }
        if (lane == 0) { cdist[w] = bv; candk[w] = bi; }
        __syncthreads();
        if (t == 0) {
            float fv = cdist[0]; int fi = candk[0];
            for (int s = 1; s < 4; s++)
                if (cdist[s] < fv || (cdist[s] == fv && candk[s] < fi)) { fv = cdist[s]; fi = candk[s]; }
            bidx_s = fi;
        }
    }
    __syncthreads();

    const int bi = bidx_s;
    atomicAdd(&g_dw[(size_t)bi * DDIM + t], zrow[t]);
    if (t == 0) {
        atomicAdd(&g_counts[bi], 1.0f);
        g_idx[n] = bi;
        out[O_IDX + n] = (float)bi;
    }
}

// ---------------------------------------------------------------- finalize
__global__ void finalize_kernel(const float* __restrict__ ema_count,
                                const float* __restrict__ ema_weight,
                                float* __restrict__ out) {
    int k = blockIdx.x, d = threadIdx.x;
    float cnt = ema_count[k] * 0.99f + 0.01f * g_counts[k];
    float w = ema_weight[(size_t)k * DDIM + d] * 0.99f + 0.01f * g_dw[(size_t)k * DDIM + d];
    out[O_WT + (size_t)k * DDIM + d] = w;
    out[O_CB + (size_t)k * DDIM + d] = w / fmaxf(cnt, 1.0f);
    if (d == 0) out[O_CNT + k] = cnt;
}

// ---------------------------------------------------------------- z_q output
__global__ void zq_kernel(const float* __restrict__ z,
                          const float* __restrict__ cb,
                          float* __restrict__ out) {
    __shared__ float q[32 * 129];
    const int n0 = blockIdx.x * 32;
    const int b = n0 >> 10, hw0 = n0 & (HWSZ - 1);
    for (int j = threadIdx.x; j < 32 * 128; j += 256) {
        int p = j >> 7, d = j & 127;
        q[p * 129 + d] = cb[(size_t)g_idx[n0 + p] * DDIM + d];
    }
    __syncthreads();
    const float* zp = z + (size_t)b * DDIM * HWSZ + hw0;
    float* op = out + O_ZQ + (size_t)b * DDIM * HWSZ + hw0;
    for (int j = threadIdx.x; j < 32 * 128; j += 256) {
        int d = j >> 5, p = j & 31;
        float ze = zp[(size_t)d * HWSZ + p];
        float zq = q[p * 129 + d];
        op[(size_t)d * HWSZ + p] = ze + (zq - ze);
    }
}

// ---------------------------------------------------------------- launch
extern "C" void kernel_launch(void* const* d_in, const int* in_sizes, int n_in,
                              void* d_out, int out_size) {
    const float* z_e        = (const float*)d_in[0];
    const float* codebook   = (const float*)d_in[1];
    const float* ema_count  = (const float*)d_in[2];
    const float* ema_weight = (const float*)d_in[3];
    float* out = (float*)d_out;

    const int SMEM_DYN = MTILE * ZSTRIDE * 2 + NBUF * BUFB;  // 34816 + 55296 = 90112
    static int smem_set = 0;
    if (!smem_set) {
        cudaFuncSetAttribute(dist_kernel, cudaFuncAttributeMaxDynamicSharedMemorySize, SMEM_DYN);
        smem_set = 1;
    }

    prep_cb_kernel<<<KCODES, 128>>>(codebook);
    prep_z_kernel<<<NPTS / 32, 256>>>(z_e);
    dist_kernel<<<NITEMS, 256, SMEM_DYN>>>();
    scan_kernel<<<NPTS, 128>>>(codebook, out);
    finalize_kernel<<<KCODES, 128>>>(ema_count, ema_weight, out);
    zq_kernel<<<NPTS / 32, 256>>>(z_e, codebook, out);
}

// round 15
// speedup vs baseline: 2.9439x; 2.9439x over previous
#include <cuda_runtime.h>
#include <cuda_fp16.h>
#include <cstdint>

// ---------------------------------------------------------------- constants
#define NPTS    16384
#define KCODES  8192
#define DDIM    128
#define HWSZ    1024
#define MTILE   128                 // points per item
#define CTILE   128                 // codes per code-tile (per stage)
#define NSPLIT  16                  // K-splits (512 codes each)
#define KPER    (KCODES / NSPLIT)   // 512
#define NCT     (KPER / CTILE)      // 4
#define NSTAGES (NCT * 2)           // 8 (2 k-chunks per code-tile)
#define NITEMS  (NSPLIT * (NPTS / MTILE))  // 2048
#define ZSTRIDE 136                 // halves per zs row (128 + 8 pad)
#define BSTRIDE 72                  // halves per B row (64 + 8 pad)
#define BUFB    (CTILE * BSTRIDE * 2)     // 18432 B
#define NBUF    3

// Output layout (concatenated float32 outputs)
#define O_ZQ  0
#define O_IDX 2097152
#define O_CB  2113536
#define O_CNT 3162112
#define O_WT  3170304

// ---------------------------------------------------------------- scratch
__device__ float  g_cnorm[KCODES];
__device__ float  g_cnh[KCODES];                    // (cnorm - 256)/2
__device__ float  g_cmax2;                          // max ||c||^2
__device__ __half g_bext[2u * KCODES * 64];         // [chunk(hi0,hi1)][code][64]
__device__ __half g_zext[NPTS * DDIM];              // fp16(z) rows (row-major in n)
__device__ float  g_zf[NPTS * DDIM];                // fp32 z rows
__device__ float  g_znorm[NPTS];
// NOTE: plain `char` is UNSIGNED on the aarch64 toolchain — must be signed char.
__device__ __align__(16) signed char g_q8[(size_t)NPTS * KCODES];  // s8 (dist-256)/2
__device__ int    g_idx[NPTS];
__device__ float  g_counts[KCODES];
__device__ float  g_dw[KCODES * DDIM];

// ---------------------------------------------------------------- helpers
__device__ __forceinline__ uint32_t smem_u32(const void* p) {
    uint32_t a;
    asm("{ .reg .u64 t; cvta.to.shared.u64 t, %1; cvt.u32.u64 %0, t; }" : "=r"(a) : "l"(p));
    return a;
}
__device__ __forceinline__ void cp_async16(uint32_t dst, const void* src) {
    asm volatile("cp.async.cg.shared.global [%0], [%1], 16;" :: "r"(dst), "l"(src) : "memory");
}
#define CP_COMMIT() asm volatile("cp.async.commit_group;" ::: "memory")
#define CP_WAIT1()  asm volatile("cp.async.wait_group 1;" ::: "memory")
#define CP_WAIT0()  asm volatile("cp.async.wait_group 0;" ::: "memory")

#define LDSM4(r0, r1, r2, r3, a)                                              \
    asm volatile("ldmatrix.sync.aligned.m8n8.x4.shared.b16 {%0,%1,%2,%3}, [%4];" \
                 : "=r"(r0), "=r"(r1), "=r"(r2), "=r"(r3) : "r"(a))

#define MMA16816(c, a0, a1, a2, a3, b0, b1)                                  \
    asm volatile("mma.sync.aligned.m16n8k16.row.col.f32.f16.f16.f32 "        \
                 "{%0,%1,%2,%3}, {%4,%5,%6,%7}, {%8,%9}, {%0,%1,%2,%3};"     \
                 : "+f"((c)[0]), "+f"((c)[1]), "+f"((c)[2]), "+f"((c)[3])    \
                 : "r"(a0), "r"(a1), "r"(a2), "r"(a3), "r"(b0), "r"(b1))

__device__ __forceinline__ int sx8(uint32_t u, int byi) {   // signed byte extract
    return (int)(signed char)((u >> (byi * 8)) & 0xffu);
}
__device__ __forceinline__ int cvt_s8_sat(float f) {        // fused round+saturate
    int q;
    asm("cvt.rni.sat.s8.f32 %0, %1;" : "=r"(q) : "f"(f));
    return q;
}

// ---------------------------------------------------------------- init
__global__ void zero_kernel() { g_cmax2 = 0.0f; }

// ---------------------------------------------------------------- prep: codebook
__global__ void prep_cb_kernel(const float* __restrict__ cb) {
    int k = blockIdx.x, t = threadIdx.x;
    float v = cb[k * DDIM + t];
    g_dw[k * DDIM + t] = 0.0f;

    int half_ = t >> 6, pos = t & 63;
    g_bext[(size_t)half_ * (KCODES * 64) + (size_t)k * 64 + pos] = __float2half_rn(v);

    float sq = v * v;
    #pragma unroll
    for (int o = 16; o > 0; o >>= 1) sq += __shfl_down_sync(0xffffffffu, sq, o);
    __shared__ float red[4];
    if ((t & 31) == 0) red[t >> 5] = sq;
    __syncthreads();
    if (t == 0) {
        float cn = red[0] + red[1] + red[2] + red[3];
        g_cnorm[k] = cn;
        g_cnh[k] = (cn - 256.0f) * 0.5f;
        g_counts[k] = 0.0f;
        atomicMax((int*)&g_cmax2, __float_as_int(cn));
    }
}

// ---------------------------------------------------------------- prep: z side
__global__ void prep_z_kernel(const float* __restrict__ z) {
    __shared__ float zsm[32 * 129];
    const int tid = threadIdx.x;
    const int n0 = blockIdx.x * 32;
    const int b = n0 >> 10, hw0 = n0 & (HWSZ - 1);
    const float* zb = z + (size_t)b * DDIM * HWSZ + hw0;
    for (int i = tid; i < 32 * DDIM; i += 256) {
        int d = i >> 5, p = i & 31;
        zsm[p * 129 + d] = zb[(size_t)d * HWSZ + p];
    }
    __syncthreads();
    uint32_t* oh = reinterpret_cast<uint32_t*>(g_zext + (size_t)n0 * DDIM);
    for (int i = tid; i < 32 * 64; i += 256) {
        int p = i >> 6, c = i & 63;
        __half2 hh = __halves2half2(__float2half_rn(zsm[p * 129 + 2 * c]),
                                    __float2half_rn(zsm[p * 129 + 2 * c + 1]));
        oh[p * 64 + c] = *reinterpret_cast<uint32_t*>(&hh);
    }
    for (int i = tid; i < 32 * DDIM; i += 256) {
        int p = i >> 7, d = i & 127;
        g_zf[(size_t)(n0 + p) * DDIM + d] = zsm[p * 129 + d];
    }
    const int lane = tid & 31, w = tid >> 5;
    for (int pt = w; pt < 32; pt += 8) {
        float s2 = 0.0f;
        #pragma unroll
        for (int i = 0; i < 4; i++) { float v = zsm[pt * 129 + lane + i * 32]; s2 += v * v; }
        #pragma unroll
        for (int o = 16; o > 0; o >>= 1) s2 += __shfl_down_sync(0xffffffffu, s2, o);
        if (lane == 0) g_znorm[n0 + pt] = sqrtf(s2);
    }
}

// ---------------------------------------------------------------- pass1: approx dist GEMM (s8)
// grid = 2048 items, block = 256 (8 warps: 4M x 2N), warp tile 32x64, 2 CTAs/SM.
__global__ void __launch_bounds__(256, 2) dist_kernel() {
    extern __shared__ char smem[];
    char* bbase = smem + MTILE * ZSTRIDE * 2;

    const int tid = threadIdx.x;
    const int lane = tid & 31, wid = tid >> 5;
    const int wm = wid & 3;        // 4 M blocks of 32
    const int wn = wid >> 2;       // 2 N blocks of 64

    const int item = blockIdx.x;
    const int ksplit = item >> 7;          // 0..15
    const int tile = item & 127;
    const int kbeg = ksplit * KPER;
    const int pbase = tile * MTILE;

    const uint32_t zs32 = smem_u32(smem);
    const uint32_t bb32 = smem_u32(bbase);

    // z tile (group 0): 128 rows x 256B into padded 272B rows
    {
        const char* zsrc = (const char*)(g_zext + (size_t)tile * MTILE * DDIM);
        for (int j = tid; j < 2048; j += 256) {
            int row = j >> 4, c16 = j & 15;
            cp_async16(zs32 + (uint32_t)row * 272u + (uint32_t)c16 * 16u,
                       zsrc + (size_t)row * 256 + (size_t)c16 * 16);
        }
        CP_COMMIT();
    }

    const uint32_t za0 = zs32 + 2u * ((wm * 32 + (lane & 15)) * ZSTRIDE + (lane >> 4) * 8);
    const uint32_t bb0 = 2u * ((wn * 64 + (lane & 15)) * BSTRIDE + (lane >> 4) * 8);

    auto issue = [&](int s) {
        int ct = s >> 1, c = s & 1;
        const char* src = (const char*)(g_bext +
            ((size_t)c * KCODES + (size_t)(kbeg + ct * CTILE)) * 64);
        uint32_t dst = bb32 + (uint32_t)(s % NBUF) * BUFB;
        #pragma unroll
        for (int i = 0; i < 4; i++) {
            int idx = tid + i * 256;          // 0..1023 16B chunks (128 rows x 8)
            cp_async16(dst + (uint32_t)(idx >> 3) * 144u + (uint32_t)(idx & 7) * 16u,
                       src + (size_t)idx * 16);
        }
        CP_COMMIT();
    };

    float acc[2][8][4];
    issue(0);
    issue(1);

    for (int s = 0; s < NSTAGES; s++) {
        const int ct = s >> 1, c = s & 1;
        if (s + 1 < NSTAGES) CP_WAIT1(); else CP_WAIT0();
        __syncthreads();
        if (s + 2 < NSTAGES) issue(s + 2);

        if (c == 0) {
            #pragma unroll
            for (int mt = 0; mt < 2; mt++)
                #pragma unroll
                for (int nt = 0; nt < 8; nt++)
                    #pragma unroll
                    for (int r = 0; r < 4; r++) acc[mt][nt][r] = 0.0f;
        }

        const uint32_t za = za0 + (uint32_t)c * 128u;   // chunk offset: c*64 halves
        const uint32_t bbuf = bb32 + (uint32_t)(s % NBUF) * BUFB + bb0;

        #pragma unroll
        for (int ks = 0; ks < 4; ks++) {
            uint32_t a[2][4];
            #pragma unroll
            for (int mt = 0; mt < 2; mt++)
                LDSM4(a[mt][0], a[mt][1], a[mt][2], a[mt][3],
                      za + (uint32_t)mt * (16u * ZSTRIDE * 2u) + (uint32_t)ks * 32u);
            uint32_t bf[4][4];
            #pragma unroll
            for (int np = 0; np < 4; np++)
                LDSM4(bf[np][0], bf[np][1], bf[np][2], bf[np][3],
                      bbuf + (uint32_t)np * (16u * BSTRIDE * 2u) + (uint32_t)ks * 32u);
            #pragma unroll
            for (int np = 0; np < 4; np++) {
                #pragma unroll
                for (int mt = 0; mt < 2; mt++)
                    MMA16816(acc[mt][2 * np], a[mt][0], a[mt][1], a[mt][2], a[mt][3],
                             bf[np][0], bf[np][2]);
                #pragma unroll
                for (int mt = 0; mt < 2; mt++)
                    MMA16816(acc[mt][2 * np + 1], a[mt][0], a[mt][1], a[mt][2], a[mt][3],
                             bf[np][1], bf[np][3]);
            }
        }

        if (c == 1) {
            // q = sat_s8(rni(cnh - acc)) — numerically identical to
            // clamp(__float2int_rn((cn - 2*acc - 256)*0.5)) within 1 ulp,
            // covered by the scan's +2 threshold margin. Byte-position
            // contract unchanged: pos = (lane&3)*16 + nt*2 + b within each
            // 64-code group <-> code = (lane&3)*2 + nt*8 + b.
            const int kk0 = kbeg + ct * CTILE + wn * 64 + (lane & 3) * 2;
            float2 ch[8];
            #pragma unroll
            for (int nt = 0; nt < 8; nt++)
                ch[nt] = __ldg(reinterpret_cast<const float2*>(g_cnh + kk0 + nt * 8));
            const int pcol = kbeg + ct * CTILE + wn * 64 + (lane & 3) * 16;   // bytes
            #pragma unroll
            for (int mt = 0; mt < 2; mt++) {
                #pragma unroll
                for (int hf = 0; hf < 2; hf++) {
                    const int row = pbase + wm * 32 + mt * 16 + (lane >> 2) + hf * 8;
                    uint32_t pq[8];
                    #pragma unroll
                    for (int nt = 0; nt < 8; nt++) {
                        int q0 = cvt_s8_sat(ch[nt].x - acc[mt][nt][hf * 2]);
                        int q1 = cvt_s8_sat(ch[nt].y - acc[mt][nt][hf * 2 + 1]);
                        pq[nt] = __byte_perm((uint32_t)q0, (uint32_t)q1, 0x0040);
                    }
                    uint32_t r32[4];
                    #pragma unroll
                    for (int p2 = 0; p2 < 4; p2++)
                        r32[p2] = __byte_perm(pq[2 * p2], pq[2 * p2 + 1], 0x5410);
                    *reinterpret_cast<int4*>(g_q8 + (size_t)row * KCODES + pcol) =
                        make_int4((int)r32[0], (int)r32[1], (int)r32[2], (int)r32[3]);
                }
            }
        }
    }
}

// ---------------------------------------------------------------- scan + exact repair + EMA accum
// (verbatim from the passing Round-13 kernel)
__global__ void __launch_bounds__(128) scan_kernel(const float* __restrict__ cb,
                                                   float* __restrict__ out) {
    __shared__ float zrow[DDIM];
    __shared__ int   candk[128];
    __shared__ float cdist[128];
    __shared__ int   wmin[4];
    __shared__ int   ccnt, covf, bidx_s;

    const int n = blockIdx.x, t = threadIdx.x;
    const int lane = t & 31, w = t >> 5;

    zrow[t] = g_zf[(size_t)n * DDIM + t];
    if (t == 0) { ccnt = 0; covf = 0; }
    __syncthreads();

    const int4* qrow = reinterpret_cast<const int4*>(g_q8 + (size_t)n * KCODES);
    int4 v[4];
    int mn = 127;
    #pragma unroll
    for (int i = 0; i < 4; i++) {
        v[i] = qrow[t + i * 128];
        const uint32_t uu[4] = { (uint32_t)v[i].x, (uint32_t)v[i].y,
                                 (uint32_t)v[i].z, (uint32_t)v[i].w };
        #pragma unroll
        for (int j = 0; j < 4; j++) {
            mn = min(mn, sx8(uu[j], 0));
            mn = min(mn, sx8(uu[j], 1));
            mn = min(mn, sx8(uu[j], 2));
            mn = min(mn, sx8(uu[j], 3));
        }
    }
    #pragma unroll
    for (int off = 16; off > 0; off >>= 1) mn = min(mn, __shfl_xor_sync(0xffffffffu, mn, off));
    if (lane == 0) wmin[w] = mn;
    __syncthreads();
    const int mnAll = min(min(wmin[0], wmin[1]), min(wmin[2], wmin[3]));

    const float zn = g_znorm[n];
    const float e = 2.0f * (2.01f * zn * sqrtf(g_cmax2) * (1.0f / 2048.0f)) + 0.01f;
    const int T = mnAll + (int)(1.0f + e) + 2;

    #pragma unroll
    for (int i = 0; i < 4; i++) {
        const int pb = (t + i * 128) * 16;
        const uint32_t uu[4] = { (uint32_t)v[i].x, (uint32_t)v[i].y,
                                 (uint32_t)v[i].z, (uint32_t)v[i].w };
        #pragma unroll
        for (int j = 0; j < 4; j++) {
            #pragma unroll
            for (int byi = 0; byi < 4; byi++) {
                int q = sx8(uu[j], byi);
                if (q <= T) {
                    int pos = pb + j * 4 + byi;
                    int k = (pos & ~63) | (((pos >> 1) & 7) << 3) |
                            (((pos >> 4) & 3) << 1) | (pos & 1);
                    int slot = atomicAdd(&ccnt, 1);
                    if (slot < 128) candk[slot] = k; else covf = 1;
                }
            }
        }
    }
    __syncthreads();

    const int cnt = min(ccnt, 128);
    if (!covf && cnt > 0) {
        const float4* z4p = reinterpret_cast<const float4*>(zrow);
        for (int s = w; s < cnt; s += 4) {
            const int k = candk[s];
            const float4 c4 = __ldg(reinterpret_cast<const float4*>(cb + (size_t)k * DDIM) + lane);
            const float4 z4 = z4p[lane];
            float d = c4.x * z4.x + c4.y * z4.y + c4.z * z4.z + c4.w * z4.w;
            #pragma unroll
            for (int off = 16; off > 0; off >>= 1) d += __shfl_xor_sync(0xffffffffu, d, off);
            if (lane == 0) cdist[s] = __ldg(g_cnorm + k) - 2.0f * d;
        }
        __syncthreads();
        if (t == 0) {
            float bv = cdist[0]; int bi = candk[0];
            for (int s = 1; s < cnt; s++) {
                float dv = cdist[s]; int kv = candk[s];
                if (dv < bv || (dv == bv && kv < bi)) { bv = dv; bi = kv; }
            }
            bidx_s = bi;
        }
    } else {
        float bv = 3.402823466e38f; int bi = 0x7fffffff;
        for (int k = t; k < KCODES; k += 128) {
            float d = 0.0f;
            #pragma unroll 8
            for (int dd = 0; dd < DDIM; dd++) d += zrow[dd] * __ldg(cb + (size_t)k * DDIM + dd);
            float dist = __ldg(g_cnorm + k) - 2.0f * d;
            if (dist < bv || (dist == bv && k < bi)) { bv = dist; bi = k; }
        }
        #pragma unroll
        for (int off = 16; off > 0; off >>= 1) {
            float ov = __shfl_xor_sync(0xffffffffu, bv, off);
            int   oi = __shfl_xor_sync(0xffffffffu, bi, off);
            if (ov < bv || (ov == bv && oi < bi)) { bv = ov; bi = oi; }
        }
        if (lane == 0) { cdist[w] = bv; candk[w] = bi; }
        __syncthreads();
        if (t == 0) {
            float fv = cdist[0]; int fi = candk[0];
            for (int s = 1; s < 4; s++)
                if (cdist[s] < fv || (cdist[s] == fv && candk[s] < fi)) { fv = cdist[s]; fi = candk[s]; }
            bidx_s = fi;
        }
    }
    __syncthreads();

    const int bi = bidx_s;
    atomicAdd(&g_dw[(size_t)bi * DDIM + t], zrow[t]);
    if (t == 0) {
        atomicAdd(&g_counts[bi], 1.0f);
        g_idx[n] = bi;
        out[O_IDX + n] = (float)bi;
    }
}

// ---------------------------------------------------------------- finalize
__global__ void finalize_kernel(const float* __restrict__ ema_count,
                                const float* __restrict__ ema_weight,
                                float* __restrict__ out) {
    int k = blockIdx.x, d = threadIdx.x;
    float cnt = ema_count[k] * 0.99f + 0.01f * g_counts[k];
    float w = ema_weight[(size_t)k * DDIM + d] * 0.99f + 0.01f * g_dw[(size_t)k * DDIM + d];
    out[O_WT + (size_t)k * DDIM + d] = w;
    out[O_CB + (size_t)k * DDIM + d] = w / fmaxf(cnt, 1.0f);
    if (d == 0) out[O_CNT + k] = cnt;
}

// ---------------------------------------------------------------- z_q output
__global__ void zq_kernel(const float* __restrict__ z,
                          const float* __restrict__ cb,
                          float* __restrict__ out) {
    __shared__ float q[32 * 129];
    const int n0 = blockIdx.x * 32;
    const int b = n0 >> 10, hw0 = n0 & (HWSZ - 1);
    for (int j = threadIdx.x; j < 32 * 128; j += 256) {
        int p = j >> 7, d = j & 127;
        q[p * 129 + d] = cb[(size_t)g_idx[n0 + p] * DDIM + d];
    }
    __syncthreads();
    const float* zp = z + (size_t)b * DDIM * HWSZ + hw0;
    float* op = out + O_ZQ + (size_t)b * DDIM * HWSZ + hw0;
    for (int j = threadIdx.x; j < 32 * 128; j += 256) {
        int d = j >> 5, p = j & 31;
        float ze = zp[(size_t)d * HWSZ + p];
        float zq = q[p * 129 + d];
        op[(size_t)d * HWSZ + p] = ze + (zq - ze);
    }
}

// ---------------------------------------------------------------- launch
extern "C" void kernel_launch(void* const* d_in, const int* in_sizes, int n_in,
                              void* d_out, int out_size) {
    const float* z_e        = (const float*)d_in[0];
    const float* codebook   = (const float*)d_in[1];
    const float* ema_count  = (const float*)d_in[2];
    const float* ema_weight = (const float*)d_in[3];
    float* out = (float*)d_out;

    const int SMEM_DYN = MTILE * ZSTRIDE * 2 + NBUF * BUFB;  // 34816 + 55296 = 90112
    static int smem_set = 0;
    if (!smem_set) {
        cudaFuncSetAttribute(dist_kernel, cudaFuncAttributeMaxDynamicSharedMemorySize, SMEM_DYN);
        smem_set = 1;
    }

    zero_kernel<<<1, 1>>>();
    prep_cb_kernel<<<KCODES, 128>>>(codebook);
    prep_z_kernel<<<NPTS / 32, 256>>>(z_e);
    dist_kernel<<<NITEMS, 256, SMEM_DYN>>>();
    scan_kernel<<<NPTS, 128>>>(codebook, out);
    finalize_kernel<<<KCODES, 128>>>(ema_count, ema_weight, out);
    zq_kernel<<<NPTS / 32, 256>>>(z_e, codebook, out);
}

// round 16
// speedup vs baseline: 3.3397x; 1.1345x over previous
#include <cuda_runtime.h>
#include <cuda_fp16.h>
#include <cstdint>

// ---------------------------------------------------------------- constants
#define NPTS    16384
#define KCODES  8192
#define DDIM    128
#define HWSZ    1024
#define MTILE   128                 // points per item
#define CTILE   128                 // codes per code-tile (per stage)
#define NSPLIT  16                  // K-splits (512 codes each)
#define KPER    (KCODES / NSPLIT)   // 512
#define NCT     (KPER / CTILE)      // 4
#define NSTAGES (NCT * 2)           // 8 (2 k-chunks per code-tile)
#define NITEMS  (NSPLIT * (NPTS / MTILE))  // 2048
#define ZSTRIDE 136                 // halves per zs row (128 + 8 pad)
#define BSTRIDE 72                  // halves per B row (64 + 8 pad)
#define BUFB    (CTILE * BSTRIDE * 2)     // 18432 B
#define NBUF    3

// Output layout (concatenated float32 outputs)
#define O_ZQ  0
#define O_IDX 2097152
#define O_CB  2113536
#define O_CNT 3162112
#define O_WT  3170304

// ---------------------------------------------------------------- scratch
__device__ float  g_cnorm[KCODES];
__device__ float  g_cnh[KCODES];                    // (cnorm - 256)/2
__device__ float  g_cmax2;                          // max ||c||^2
__device__ __half g_bext[2u * KCODES * 64];         // [chunk(hi0,hi1)][code][64]
__device__ __half g_zext[NPTS * DDIM];              // fp16(z) rows (row-major in n)
__device__ float  g_zf[NPTS * DDIM];                // fp32 z rows
__device__ float  g_znorm[NPTS];
// NOTE: plain `char` is UNSIGNED on the aarch64 toolchain — must be signed char.
__device__ __align__(16) signed char g_q8[(size_t)NPTS * KCODES];  // s8 (dist-256)/2
__device__ int    g_idx[NPTS];
__device__ float  g_counts[KCODES];
__device__ float  g_dw[KCODES * DDIM];

// ---------------------------------------------------------------- helpers
__device__ __forceinline__ uint32_t smem_u32(const void* p) {
    uint32_t a;
    asm("{ .reg .u64 t; cvta.to.shared.u64 t, %1; cvt.u32.u64 %0, t; }" : "=r"(a) : "l"(p));
    return a;
}
__device__ __forceinline__ void cp_async16(uint32_t dst, const void* src) {
    asm volatile("cp.async.cg.shared.global [%0], [%1], 16;" :: "r"(dst), "l"(src) : "memory");
}
#define CP_COMMIT() asm volatile("cp.async.commit_group;" ::: "memory")
#define CP_WAIT1()  asm volatile("cp.async.wait_group 1;" ::: "memory")
#define CP_WAIT0()  asm volatile("cp.async.wait_group 0;" ::: "memory")

#define LDSM4(r0, r1, r2, r3, a)                                              \
    asm volatile("ldmatrix.sync.aligned.m8n8.x4.shared.b16 {%0,%1,%2,%3}, [%4];" \
                 : "=r"(r0), "=r"(r1), "=r"(r2), "=r"(r3) : "r"(a))

#define MMA16816(c, a0, a1, a2, a3, b0, b1)                                  \
    asm volatile("mma.sync.aligned.m16n8k16.row.col.f32.f16.f16.f32 "        \
                 "{%0,%1,%2,%3}, {%4,%5,%6,%7}, {%8,%9}, {%0,%1,%2,%3};"     \
                 : "+f"((c)[0]), "+f"((c)[1]), "+f"((c)[2]), "+f"((c)[3])    \
                 : "r"(a0), "r"(a1), "r"(a2), "r"(a3), "r"(b0), "r"(b1))

__device__ __forceinline__ int sx8(uint32_t u, int byi) {   // signed byte extract
    return (int)(signed char)((u >> (byi * 8)) & 0xffu);
}
__device__ __forceinline__ int cvt_s8_sat(float f) {        // fused round+saturate
    int q;
    asm("cvt.rni.sat.s8.f32 %0, %1;" : "=r"(q) : "f"(f));
    return q;
}

// ---------------------------------------------------------------- init
__global__ void zero_kernel() { g_cmax2 = 0.0f; }

// ---------------------------------------------------------------- prep: codebook
__global__ void prep_cb_kernel(const float* __restrict__ cb) {
    int k = blockIdx.x, t = threadIdx.x;
    float v = cb[k * DDIM + t];
    g_dw[k * DDIM + t] = 0.0f;

    int half_ = t >> 6, pos = t & 63;
    g_bext[(size_t)half_ * (KCODES * 64) + (size_t)k * 64 + pos] = __float2half_rn(v);

    float sq = v * v;
    #pragma unroll
    for (int o = 16; o > 0; o >>= 1) sq += __shfl_down_sync(0xffffffffu, sq, o);
    __shared__ float red[4];
    if ((t & 31) == 0) red[t >> 5] = sq;
    __syncthreads();
    if (t == 0) {
        float cn = red[0] + red[1] + red[2] + red[3];
        g_cnorm[k] = cn;
        g_cnh[k] = (cn - 256.0f) * 0.5f;
        g_counts[k] = 0.0f;
        atomicMax((int*)&g_cmax2, __float_as_int(cn));
    }
}

// ---------------------------------------------------------------- prep: z side
__global__ void prep_z_kernel(const float* __restrict__ z) {
    __shared__ float zsm[32 * 129];
    const int tid = threadIdx.x;
    const int n0 = blockIdx.x * 32;
    const int b = n0 >> 10, hw0 = n0 & (HWSZ - 1);
    const float* zb = z + (size_t)b * DDIM * HWSZ + hw0;
    for (int i = tid; i < 32 * DDIM; i += 256) {
        int d = i >> 5, p = i & 31;
        zsm[p * 129 + d] = zb[(size_t)d * HWSZ + p];
    }
    __syncthreads();
    uint32_t* oh = reinterpret_cast<uint32_t*>(g_zext + (size_t)n0 * DDIM);
    for (int i = tid; i < 32 * 64; i += 256) {
        int p = i >> 6, c = i & 63;
        __half2 hh = __halves2half2(__float2half_rn(zsm[p * 129 + 2 * c]),
                                    __float2half_rn(zsm[p * 129 + 2 * c + 1]));
        oh[p * 64 + c] = *reinterpret_cast<uint32_t*>(&hh);
    }
    for (int i = tid; i < 32 * DDIM; i += 256) {
        int p = i >> 7, d = i & 127;
        g_zf[(size_t)(n0 + p) * DDIM + d] = zsm[p * 129 + d];
    }
    const int lane = tid & 31, w = tid >> 5;
    for (int pt = w; pt < 32; pt += 8) {
        float s2 = 0.0f;
        #pragma unroll
        for (int i = 0; i < 4; i++) { float v = zsm[pt * 129 + lane + i * 32]; s2 += v * v; }
        #pragma unroll
        for (int o = 16; o > 0; o >>= 1) s2 += __shfl_down_sync(0xffffffffu, s2, o);
        if (lane == 0) g_znorm[n0 + pt] = sqrtf(s2);
    }
}

// ---------------------------------------------------------------- pass1: approx dist GEMM (s8)
// grid = 2048 items, block = 256 (8 warps: 4M x 2N), warp tile 32x64, 2 CTAs/SM.
__global__ void __launch_bounds__(256, 2) dist_kernel() {
    extern __shared__ char smem[];
    char* bbase = smem + MTILE * ZSTRIDE * 2;

    const int tid = threadIdx.x;
    const int lane = tid & 31, wid = tid >> 5;
    const int wm = wid & 3;        // 4 M blocks of 32
    const int wn = wid >> 2;       // 2 N blocks of 64

    const int item = blockIdx.x;
    const int ksplit = item >> 7;          // 0..15
    const int tile = item & 127;
    const int kbeg = ksplit * KPER;
    const int pbase = tile * MTILE;

    const uint32_t zs32 = smem_u32(smem);
    const uint32_t bb32 = smem_u32(bbase);

    // z tile (group 0): 128 rows x 256B into padded 272B rows
    {
        const char* zsrc = (const char*)(g_zext + (size_t)tile * MTILE * DDIM);
        for (int j = tid; j < 2048; j += 256) {
            int row = j >> 4, c16 = j & 15;
            cp_async16(zs32 + (uint32_t)row * 272u + (uint32_t)c16 * 16u,
                       zsrc + (size_t)row * 256 + (size_t)c16 * 16);
        }
        CP_COMMIT();
    }

    const uint32_t za0 = zs32 + 2u * ((wm * 32 + (lane & 15)) * ZSTRIDE + (lane >> 4) * 8);
    const uint32_t bb0 = 2u * ((wn * 64 + (lane & 15)) * BSTRIDE + (lane >> 4) * 8);

    auto issue = [&](int s) {
        int ct = s >> 1, c = s & 1;
        const char* src = (const char*)(g_bext +
            ((size_t)c * KCODES + (size_t)(kbeg + ct * CTILE)) * 64);
        uint32_t dst = bb32 + (uint32_t)(s % NBUF) * BUFB;
        #pragma unroll
        for (int i = 0; i < 4; i++) {
            int idx = tid + i * 256;          // 0..1023 16B chunks (128 rows x 8)
            cp_async16(dst + (uint32_t)(idx >> 3) * 144u + (uint32_t)(idx & 7) * 16u,
                       src + (size_t)idx * 16);
        }
        CP_COMMIT();
    };

    float acc[2][8][4];
    issue(0);
    issue(1);

    for (int s = 0; s < NSTAGES; s++) {
        const int ct = s >> 1, c = s & 1;
        if (s + 1 < NSTAGES) CP_WAIT1(); else CP_WAIT0();
        __syncthreads();
        if (s + 2 < NSTAGES) issue(s + 2);

        if (c == 0) {
            #pragma unroll
            for (int mt = 0; mt < 2; mt++)
                #pragma unroll
                for (int nt = 0; nt < 8; nt++)
                    #pragma unroll
                    for (int r = 0; r < 4; r++) acc[mt][nt][r] = 0.0f;
        }

        const uint32_t za = za0 + (uint32_t)c * 128u;   // chunk offset: c*64 halves
        const uint32_t bbuf = bb32 + (uint32_t)(s % NBUF) * BUFB + bb0;

        #pragma unroll
        for (int ks = 0; ks < 4; ks++) {
            uint32_t a[2][4];
            #pragma unroll
            for (int mt = 0; mt < 2; mt++)
                LDSM4(a[mt][0], a[mt][1], a[mt][2], a[mt][3],
                      za + (uint32_t)mt * (16u * ZSTRIDE * 2u) + (uint32_t)ks * 32u);
            uint32_t bf[4][4];
            #pragma unroll
            for (int np = 0; np < 4; np++)
                LDSM4(bf[np][0], bf[np][1], bf[np][2], bf[np][3],
                      bbuf + (uint32_t)np * (16u * BSTRIDE * 2u) + (uint32_t)ks * 32u);
            #pragma unroll
            for (int np = 0; np < 4; np++) {
                #pragma unroll
                for (int mt = 0; mt < 2; mt++)
                    MMA16816(acc[mt][2 * np], a[mt][0], a[mt][1], a[mt][2], a[mt][3],
                             bf[np][0], bf[np][2]);
                #pragma unroll
                for (int mt = 0; mt < 2; mt++)
                    MMA16816(acc[mt][2 * np + 1], a[mt][0], a[mt][1], a[mt][2], a[mt][3],
                             bf[np][1], bf[np][3]);
            }
        }

        if (c == 1) {
            // q = sat_s8(rni(cnh - acc)); byte-position contract unchanged:
            // pos = (lane&3)*16 + nt*2 + b <-> code = (lane&3)*2 + nt*8 + b.
            const int kk0 = kbeg + ct * CTILE + wn * 64 + (lane & 3) * 2;
            float2 ch[8];
            #pragma unroll
            for (int nt = 0; nt < 8; nt++)
                ch[nt] = __ldg(reinterpret_cast<const float2*>(g_cnh + kk0 + nt * 8));
            const int pcol = kbeg + ct * CTILE + wn * 64 + (lane & 3) * 16;   // bytes
            #pragma unroll
            for (int mt = 0; mt < 2; mt++) {
                #pragma unroll
                for (int hf = 0; hf < 2; hf++) {
                    const int row = pbase + wm * 32 + mt * 16 + (lane >> 2) + hf * 8;
                    uint32_t pq[8];
                    #pragma unroll
                    for (int nt = 0; nt < 8; nt++) {
                        int q0 = cvt_s8_sat(ch[nt].x - acc[mt][nt][hf * 2]);
                        int q1 = cvt_s8_sat(ch[nt].y - acc[mt][nt][hf * 2 + 1]);
                        pq[nt] = __byte_perm((uint32_t)q0, (uint32_t)q1, 0x0040);
                    }
                    uint32_t r32[4];
                    #pragma unroll
                    for (int p2 = 0; p2 < 4; p2++)
                        r32[p2] = __byte_perm(pq[2 * p2], pq[2 * p2 + 1], 0x5410);
                    *reinterpret_cast<int4*>(g_q8 + (size_t)row * KCODES + pcol) =
                        make_int4((int)r32[0], (int)r32[1], (int)r32[2], (int)r32[3]);
                }
            }
        }
    }
}

// ---------------------------------------------------------------- scan v3 + exact repair + EMA accum
// Same candidate set as R15; threshold pass uses a word-parallel byte test.
__global__ void __launch_bounds__(128) scan_kernel(const float* __restrict__ cb,
                                                   float* __restrict__ out) {
    __shared__ float zrow[DDIM];
    __shared__ int   candk[128];
    __shared__ float cdist[128];
    __shared__ int   wmin[4];
    __shared__ int   ccnt, covf, bidx_s;

    const int n = blockIdx.x, t = threadIdx.x;
    const int lane = t & 31, w = t >> 5;

    zrow[t] = g_zf[(size_t)n * DDIM + t];
    if (t == 0) { ccnt = 0; covf = 0; }
    __syncthreads();

    const int4* qrow = reinterpret_cast<const int4*>(g_q8 + (size_t)n * KCODES);
    int4 v[4];
    int mn = 127;
    #pragma unroll
    for (int i = 0; i < 4; i++) {
        v[i] = qrow[t + i * 128];
        const uint32_t uu[4] = { (uint32_t)v[i].x, (uint32_t)v[i].y,
                                 (uint32_t)v[i].z, (uint32_t)v[i].w };
        #pragma unroll
        for (int j = 0; j < 4; j++) {
            mn = min(mn, sx8(uu[j], 0));
            mn = min(mn, sx8(uu[j], 1));
            mn = min(mn, sx8(uu[j], 2));
            mn = min(mn, sx8(uu[j], 3));
        }
    }
    #pragma unroll
    for (int off = 16; off > 0; off >>= 1) mn = min(mn, __shfl_xor_sync(0xffffffffu, mn, off));
    if (lane == 0) wmin[w] = mn;
    __syncthreads();
    const int mnAll = min(min(wmin[0], wmin[1]), min(wmin[2], wmin[3]));

    const float zn = g_znorm[n];
    const float e = 2.0f * (2.01f * zn * sqrtf(g_cmax2) * (1.0f / 2048.0f)) + 0.01f;
    const int T = mnAll + (int)(1.0f + e) + 2;

    // Word-parallel candidate test: bias to unsigned (x = u ^ 0x80..),
    // "any byte < N" mask with N = T+129 (valid for T < 120; no false
    // negatives, borrow-induced false positives filtered by exact re-check).
    // For T >= 120 fall back to exact-checking every word (same semantics).
    const bool fast = (T < 120);
    const uint32_t Nb = (uint32_t)(min(T, 119) + 129) * 0x01010101u;

    #pragma unroll
    for (int i = 0; i < 4; i++) {
        const int pb = (t + i * 128) * 16;
        const uint32_t uu[4] = { (uint32_t)v[i].x, (uint32_t)v[i].y,
                                 (uint32_t)v[i].z, (uint32_t)v[i].w };
        #pragma unroll
        for (int j = 0; j < 4; j++) {
            const uint32_t u = uu[j];
            const uint32_t x = u ^ 0x80808080u;
            const uint32_t m = fast ? ((x - Nb) & ~x & 0x80808080u) : 0x80808080u;
            if (m) {
                #pragma unroll
                for (int byi = 0; byi < 4; byi++) {
                    int q = sx8(u, byi);
                    if (q <= T) {
                        int pos = pb + j * 4 + byi;
                        int k = (pos & ~63) | (((pos >> 1) & 7) << 3) |
                                (((pos >> 4) & 3) << 1) | (pos & 1);
                        int slot = atomicAdd(&ccnt, 1);
                        if (slot < 128) candk[slot] = k; else covf = 1;
                    }
                }
            }
        }
    }
    __syncthreads();

    const int cnt = min(ccnt, 128);
    if (!covf && cnt > 0) {
        const float4* z4p = reinterpret_cast<const float4*>(zrow);
        for (int s = w; s < cnt; s += 4) {
            const int k = candk[s];
            const float4 c4 = __ldg(reinterpret_cast<const float4*>(cb + (size_t)k * DDIM) + lane);
            const float4 z4 = z4p[lane];
            float d = c4.x * z4.x + c4.y * z4.y + c4.z * z4.z + c4.w * z4.w;
            #pragma unroll
            for (int off = 16; off > 0; off >>= 1) d += __shfl_xor_sync(0xffffffffu, d, off);
            if (lane == 0) cdist[s] = __ldg(g_cnorm + k) - 2.0f * d;
        }
        __syncthreads();
        if (t == 0) {
            float bv = cdist[0]; int bi = candk[0];
            for (int s = 1; s < cnt; s++) {
                float dv = cdist[s]; int kv = candk[s];
                if (dv < bv || (dv == bv && kv < bi)) { bv = dv; bi = kv; }
            }
            bidx_s = bi;
        }
    } else {
        float bv = 3.402823466e38f; int bi = 0x7fffffff;
        for (int k = t; k < KCODES; k += 128) {
            float d = 0.0f;
            #pragma unroll 8
            for (int dd = 0; dd < DDIM; dd++) d += zrow[dd] * __ldg(cb + (size_t)k * DDIM + dd);
            float dist = __ldg(g_cnorm + k) - 2.0f * d;
            if (dist < bv || (dist == bv && k < bi)) { bv = dist; bi = k; }
        }
        #pragma unroll
        for (int off = 16; off > 0; off >>= 1) {
            float ov = __shfl_xor_sync(0xffffffffu, bv, off);
            int   oi = __shfl_xor_sync(0xffffffffu, bi, off);
            if (ov < bv || (ov == bv && oi < bi)) { bv = ov; bi = oi; }
        }
        if (lane == 0) { cdist[w] = bv; candk[w] = bi; }
        __syncthreads();
        if (t == 0) {
            float fv = cdist[0]; int fi = candk[0];
            for (int s = 1; s < 4; s++)
                if (cdist[s] < fv || (cdist[s] == fv && candk[s] < fi)) { fv = cdist[s]; fi = candk[s]; }
            bidx_s = fi;
        }
    }
    __syncthreads();

    const int bi = bidx_s;
    atomicAdd(&g_dw[(size_t)bi * DDIM + t], zrow[t]);
    if (t == 0) {
        atomicAdd(&g_counts[bi], 1.0f);
        g_idx[n] = bi;
        out[O_IDX + n] = (float)bi;
    }
}

// ---------------------------------------------------------------- finalize
__global__ void finalize_kernel(const float* __restrict__ ema_count,
                                const float* __restrict__ ema_weight,
                                float* __restrict__ out) {
    int k = blockIdx.x, d = threadIdx.x;
    float cnt = ema_count[k] * 0.99f + 0.01f * g_counts[k];
    float w = ema_weight[(size_t)k * DDIM + d] * 0.99f + 0.01f * g_dw[(size_t)k * DDIM + d];
    out[O_WT + (size_t)k * DDIM + d] = w;
    out[O_CB + (size_t)k * DDIM + d] = w / fmaxf(cnt, 1.0f);
    if (d == 0) out[O_CNT + k] = cnt;
}

// ---------------------------------------------------------------- z_q output
__global__ void zq_kernel(const float* __restrict__ z,
                          const float* __restrict__ cb,
                          float* __restrict__ out) {
    __shared__ float q[32 * 129];
    const int n0 = blockIdx.x * 32;
    const int b = n0 >> 10, hw0 = n0 & (HWSZ - 1);
    for (int j = threadIdx.x; j < 32 * 128; j += 256) {
        int p = j >> 7, d = j & 127;
        q[p * 129 + d] = cb[(size_t)g_idx[n0 + p] * DDIM + d];
    }
    __syncthreads();
    const float* zp = z + (size_t)b * DDIM * HWSZ + hw0;
    float* op = out + O_ZQ + (size_t)b * DDIM * HWSZ + hw0;
    for (int j = threadIdx.x; j < 32 * 128; j += 256) {
        int d = j >> 5, p = j & 31;
        float ze = zp[(size_t)d * HWSZ + p];
        float zq = q[p * 129 + d];
        op[(size_t)d * HWSZ + p] = ze + (zq - ze);
    }
}

// ---------------------------------------------------------------- launch
extern "C" void kernel_launch(void* const* d_in, const int* in_sizes, int n_in,
                              void* d_out, int out_size) {
    const float* z_e        = (const float*)d_in[0];
    const float* codebook   = (const float*)d_in[1];
    const float* ema_count  = (const float*)d_in[2];
    const float* ema_weight = (const float*)d_in[3];
    float* out = (float*)d_out;

    const int SMEM_DYN = MTILE * ZSTRIDE * 2 + NBUF * BUFB;  // 34816 + 55296 = 90112
    static int smem_set = 0;
    if (!smem_set) {
        cudaFuncSetAttribute(dist_kernel, cudaFuncAttributeMaxDynamicSharedMemorySize, SMEM_DYN);
        smem_set = 1;
    }

    zero_kernel<<<1, 1>>>();
    prep_cb_kernel<<<KCODES, 128>>>(codebook);
    prep_z_kernel<<<NPTS / 32, 256>>>(z_e);
    dist_kernel<<<NITEMS, 256, SMEM_DYN>>>();
    scan_kernel<<<NPTS, 128>>>(codebook, out);
    finalize_kernel<<<KCODES, 128>>>(ema_count, ema_weight, out);
    zq_kernel<<<NPTS / 32, 256>>>(z_e, codebook, out);
}

// round 17
// speedup vs baseline: 3.6959x; 1.1066x over previous
#include <cuda_runtime.h>
#include <cuda_fp16.h>
#include <cstdint>

// ---------------------------------------------------------------- constants
#define NPTS    16384
#define KCODES  8192
#define DDIM    128
#define HWSZ    1024
#define MTILE   128                 // points per item
#define CTILE   128                 // codes per code-tile (per stage)
#define NSPLIT  16                  // K-splits (512 codes each)
#define KPER    (KCODES / NSPLIT)   // 512
#define NCT     (KPER / CTILE)      // 4
#define NSTAGES (NCT * 2)           // 8 (2 k-chunks per code-tile)
#define NITEMS  (NSPLIT * (NPTS / MTILE))  // 2048
#define ZSTRIDE 136                 // halves per zs row (128 + 8 pad)
#define BSTRIDE 72                  // halves per B row (64 + 8 pad)
#define BUFB    (CTILE * BSTRIDE * 2)     // 18432 B
#define NBUF    3

// Output layout (concatenated float32 outputs)
#define O_ZQ  0
#define O_IDX 2097152
#define O_CB  2113536
#define O_CNT 3162112
#define O_WT  3170304

// ---------------------------------------------------------------- scratch
__device__ float  g_cnorm[KCODES];
__device__ float  g_cnh[KCODES];                    // (cnorm - 256)/2
__device__ float  g_cmax2;                          // max ||c||^2
__device__ __half g_bext[2u * KCODES * 64];         // [chunk(hi0,hi1)][code][64]
__device__ __half g_zext[NPTS * DDIM];              // fp16(z) rows (row-major in n)
__device__ float  g_zf[NPTS * DDIM];                // fp32 z rows
__device__ float  g_znorm[NPTS];
// NOTE: plain `char` is UNSIGNED on the aarch64 toolchain — must be signed char.
__device__ __align__(16) signed char g_q8[(size_t)NPTS * KCODES];  // s8 (dist-256)/2
__device__ int    g_idx[NPTS];
__device__ float  g_counts[KCODES];
__device__ float  g_dw[KCODES * DDIM];

// ---------------------------------------------------------------- helpers
__device__ __forceinline__ uint32_t smem_u32(const void* p) {
    uint32_t a;
    asm("{ .reg .u64 t; cvta.to.shared.u64 t, %1; cvt.u32.u64 %0, t; }" : "=r"(a) : "l"(p));
    return a;
}
__device__ __forceinline__ void cp_async16(uint32_t dst, const void* src) {
    asm volatile("cp.async.cg.shared.global [%0], [%1], 16;" :: "r"(dst), "l"(src) : "memory");
}
#define CP_COMMIT() asm volatile("cp.async.commit_group;" ::: "memory")
#define CP_WAIT1()  asm volatile("cp.async.wait_group 1;" ::: "memory")
#define CP_WAIT0()  asm volatile("cp.async.wait_group 0;" ::: "memory")

#define LDSM4(r0, r1, r2, r3, a)                                              \
    asm volatile("ldmatrix.sync.aligned.m8n8.x4.shared.b16 {%0,%1,%2,%3}, [%4];" \
                 : "=r"(r0), "=r"(r1), "=r"(r2), "=r"(r3) : "r"(a))

#define MMA16816(c, a0, a1, a2, a3, b0, b1)                                  \
    asm volatile("mma.sync.aligned.m16n8k16.row.col.f32.f16.f16.f32 "        \
                 "{%0,%1,%2,%3}, {%4,%5,%6,%7}, {%8,%9}, {%0,%1,%2,%3};"     \
                 : "+f"((c)[0]), "+f"((c)[1]), "+f"((c)[2]), "+f"((c)[3])    \
                 : "r"(a0), "r"(a1), "r"(a2), "r"(a3), "r"(b0), "r"(b1))

__device__ __forceinline__ int sx8(uint32_t u, int byi) {   // signed byte extract
    return (int)(signed char)((u >> (byi * 8)) & 0xffu);
}
__device__ __forceinline__ int cvt_s8_sat(float f) {        // fused round+saturate
    int q;
    asm("cvt.rni.sat.s8.f32 %0, %1;" : "=r"(q) : "f"(f));
    return q;
}

// ---------------------------------------------------------------- init
__global__ void zero_kernel() { g_cmax2 = 0.0f; }

// ---------------------------------------------------------------- prep: codebook
__global__ void prep_cb_kernel(const float* __restrict__ cb) {
    int k = blockIdx.x, t = threadIdx.x;
    float v = cb[k * DDIM + t];
    g_dw[k * DDIM + t] = 0.0f;

    int half_ = t >> 6, pos = t & 63;
    g_bext[(size_t)half_ * (KCODES * 64) + (size_t)k * 64 + pos] = __float2half_rn(v);

    float sq = v * v;
    #pragma unroll
    for (int o = 16; o > 0; o >>= 1) sq += __shfl_down_sync(0xffffffffu, sq, o);
    __shared__ float red[4];
    if ((t & 31) == 0) red[t >> 5] = sq;
    __syncthreads();
    if (t == 0) {
        float cn = red[0] + red[1] + red[2] + red[3];
        g_cnorm[k] = cn;
        g_cnh[k] = (cn - 256.0f) * 0.5f;
        g_counts[k] = 0.0f;
        atomicMax((int*)&g_cmax2, __float_as_int(cn));
    }
}

// ---------------------------------------------------------------- prep: z side
__global__ void prep_z_kernel(const float* __restrict__ z) {
    __shared__ float zsm[32 * 129];
    const int tid = threadIdx.x;
    const int n0 = blockIdx.x * 32;
    const int b = n0 >> 10, hw0 = n0 & (HWSZ - 1);
    const float* zb = z + (size_t)b * DDIM * HWSZ + hw0;
    for (int i = tid; i < 32 * DDIM; i += 256) {
        int d = i >> 5, p = i & 31;
        zsm[p * 129 + d] = zb[(size_t)d * HWSZ + p];
    }
    __syncthreads();
    uint32_t* oh = reinterpret_cast<uint32_t*>(g_zext + (size_t)n0 * DDIM);
    for (int i = tid; i < 32 * 64; i += 256) {
        int p = i >> 6, c = i & 63;
        __half2 hh = __halves2half2(__float2half_rn(zsm[p * 129 + 2 * c]),
                                    __float2half_rn(zsm[p * 129 + 2 * c + 1]));
        oh[p * 64 + c] = *reinterpret_cast<uint32_t*>(&hh);
    }
    for (int i = tid; i < 32 * DDIM; i += 256) {
        int p = i >> 7, d = i & 127;
        g_zf[(size_t)(n0 + p) * DDIM + d] = zsm[p * 129 + d];
    }
    const int lane = tid & 31, w = tid >> 5;
    for (int pt = w; pt < 32; pt += 8) {
        float s2 = 0.0f;
        #pragma unroll
        for (int i = 0; i < 4; i++) { float v = zsm[pt * 129 + lane + i * 32]; s2 += v * v; }
        #pragma unroll
        for (int o = 16; o > 0; o >>= 1) s2 += __shfl_down_sync(0xffffffffu, s2, o);
        if (lane == 0) g_znorm[n0 + pt] = sqrtf(s2);
    }
}

// ---------------------------------------------------------------- pass1: approx dist GEMM (s8)
// grid = 2048 items, block = 256 (8 warps: 4M x 2N), warp tile 32x64, 2 CTAs/SM.
__global__ void __launch_bounds__(256, 2) dist_kernel() {
    extern __shared__ char smem[];
    char* bbase = smem + MTILE * ZSTRIDE * 2;

    const int tid = threadIdx.x;
    const int lane = tid & 31, wid = tid >> 5;
    const int wm = wid & 3;        // 4 M blocks of 32
    const int wn = wid >> 2;       // 2 N blocks of 64

    const int item = blockIdx.x;
    const int ksplit = item >> 7;          // 0..15
    const int tile = item & 127;
    const int kbeg = ksplit * KPER;
    const int pbase = tile * MTILE;

    const uint32_t zs32 = smem_u32(smem);
    const uint32_t bb32 = smem_u32(bbase);

    // z tile (group 0): 128 rows x 256B into padded 272B rows
    {
        const char* zsrc = (const char*)(g_zext + (size_t)tile * MTILE * DDIM);
        for (int j = tid; j < 2048; j += 256) {
            int row = j >> 4, c16 = j & 15;
            cp_async16(zs32 + (uint32_t)row * 272u + (uint32_t)c16 * 16u,
                       zsrc + (size_t)row * 256 + (size_t)c16 * 16);
        }
        CP_COMMIT();
    }

    const uint32_t za0 = zs32 + 2u * ((wm * 32 + (lane & 15)) * ZSTRIDE + (lane >> 4) * 8);
    const uint32_t bb0 = 2u * ((wn * 64 + (lane & 15)) * BSTRIDE + (lane >> 4) * 8);

    auto issue = [&](int s) {
        int ct = s >> 1, c = s & 1;
        const char* src = (const char*)(g_bext +
            ((size_t)c * KCODES + (size_t)(kbeg + ct * CTILE)) * 64);
        uint32_t dst = bb32 + (uint32_t)(s % NBUF) * BUFB;
        #pragma unroll
        for (int i = 0; i < 4; i++) {
            int idx = tid + i * 256;          // 0..1023 16B chunks (128 rows x 8)
            cp_async16(dst + (uint32_t)(idx >> 3) * 144u + (uint32_t)(idx & 7) * 16u,
                       src + (size_t)idx * 16);
        }
        CP_COMMIT();
    };

    float acc[2][8][4];
    issue(0);
    issue(1);

    for (int s = 0; s < NSTAGES; s++) {
        const int ct = s >> 1, c = s & 1;
        if (s + 1 < NSTAGES) CP_WAIT1(); else CP_WAIT0();
        __syncthreads();
        if (s + 2 < NSTAGES) issue(s + 2);

        if (c == 0) {
            #pragma unroll
            for (int mt = 0; mt < 2; mt++)
                #pragma unroll
                for (int nt = 0; nt < 8; nt++)
                    #pragma unroll
                    for (int r = 0; r < 4; r++) acc[mt][nt][r] = 0.0f;
        }

        const uint32_t za = za0 + (uint32_t)c * 128u;   // chunk offset: c*64 halves
        const uint32_t bbuf = bb32 + (uint32_t)(s % NBUF) * BUFB + bb0;

        #pragma unroll
        for (int ks = 0; ks < 4; ks++) {
            uint32_t a[2][4];
            #pragma unroll
            for (int mt = 0; mt < 2; mt++)
                LDSM4(a[mt][0], a[mt][1], a[mt][2], a[mt][3],
                      za + (uint32_t)mt * (16u * ZSTRIDE * 2u) + (uint32_t)ks * 32u);
            uint32_t bf[4][4];
            #pragma unroll
            for (int np = 0; np < 4; np++)
                LDSM4(bf[np][0], bf[np][1], bf[np][2], bf[np][3],
                      bbuf + (uint32_t)np * (16u * BSTRIDE * 2u) + (uint32_t)ks * 32u);
            #pragma unroll
            for (int np = 0; np < 4; np++) {
                #pragma unroll
                for (int mt = 0; mt < 2; mt++)
                    MMA16816(acc[mt][2 * np], a[mt][0], a[mt][1], a[mt][2], a[mt][3],
                             bf[np][0], bf[np][2]);
                #pragma unroll
                for (int mt = 0; mt < 2; mt++)
                    MMA16816(acc[mt][2 * np + 1], a[mt][0], a[mt][1], a[mt][2], a[mt][3],
                             bf[np][1], bf[np][3]);
            }
        }

        if (c == 1) {
            // q = sat_s8(rni(cnh - acc)); byte-position contract unchanged:
            // pos = (lane&3)*16 + nt*2 + b <-> code = (lane&3)*2 + nt*8 + b.
            const int kk0 = kbeg + ct * CTILE + wn * 64 + (lane & 3) * 2;
            float2 ch[8];
            #pragma unroll
            for (int nt = 0; nt < 8; nt++)
                ch[nt] = __ldg(reinterpret_cast<const float2*>(g_cnh + kk0 + nt * 8));
            const int pcol = kbeg + ct * CTILE + wn * 64 + (lane & 3) * 16;   // bytes
            #pragma unroll
            for (int mt = 0; mt < 2; mt++) {
                #pragma unroll
                for (int hf = 0; hf < 2; hf++) {
                    const int row = pbase + wm * 32 + mt * 16 + (lane >> 2) + hf * 8;
                    uint32_t pq[8];
                    #pragma unroll
                    for (int nt = 0; nt < 8; nt++) {
                        int q0 = cvt_s8_sat(ch[nt].x - acc[mt][nt][hf * 2]);
                        int q1 = cvt_s8_sat(ch[nt].y - acc[mt][nt][hf * 2 + 1]);
                        pq[nt] = __byte_perm((uint32_t)q0, (uint32_t)q1, 0x0040);
                    }
                    uint32_t r32[4];
                    #pragma unroll
                    for (int p2 = 0; p2 < 4; p2++)
                        r32[p2] = __byte_perm(pq[2 * p2], pq[2 * p2 + 1], 0x5410);
                    *reinterpret_cast<int4*>(g_q8 + (size_t)row * KCODES + pcol) =
                        make_int4((int)r32[0], (int)r32[1], (int)r32[2], (int)r32[3]);
                }
            }
        }
    }
}

// ---------------------------------------------------------------- scan v4 + exact repair + EMA accum
// Min pass via per-byte SIMD (__vmins4); threshold pass word-parallel (R16).
// Candidate set identical to R15/R16.
__global__ void __launch_bounds__(128) scan_kernel(const float* __restrict__ cb,
                                                   float* __restrict__ out) {
    __shared__ float zrow[DDIM];
    __shared__ int   candk[128];
    __shared__ float cdist[128];
    __shared__ uint32_t wmin4[4];
    __shared__ int   ccnt, covf, bidx_s;

    const int n = blockIdx.x, t = threadIdx.x;
    const int lane = t & 31, w = t >> 5;

    zrow[t] = g_zf[(size_t)n * DDIM + t];
    if (t == 0) { ccnt = 0; covf = 0; }
    __syncthreads();

    const int4* qrow = reinterpret_cast<const int4*>(g_q8 + (size_t)n * KCODES);
    int4 v[4];
    uint32_t m4 = 0x7f7f7f7fu;              // per-byte running signed min
    #pragma unroll
    for (int i = 0; i < 4; i++) {
        v[i] = qrow[t + i * 128];
        m4 = __vmins4(m4, (uint32_t)v[i].x);
        m4 = __vmins4(m4, (uint32_t)v[i].y);
        m4 = __vmins4(m4, (uint32_t)v[i].z);
        m4 = __vmins4(m4, (uint32_t)v[i].w);
    }
    #pragma unroll
    for (int off = 16; off > 0; off >>= 1)
        m4 = __vmins4(m4, __shfl_xor_sync(0xffffffffu, m4, off));
    if (lane == 0) wmin4[w] = m4;
    __syncthreads();
    uint32_t mAll4 = __vmins4(__vmins4(wmin4[0], wmin4[1]), __vmins4(wmin4[2], wmin4[3]));
    const int mnAll = min(min(sx8(mAll4, 0), sx8(mAll4, 1)),
                          min(sx8(mAll4, 2), sx8(mAll4, 3)));

    const float zn = g_znorm[n];
    const float e = 2.0f * (2.01f * zn * sqrtf(g_cmax2) * (1.0f / 2048.0f)) + 0.01f;
    const int T = mnAll + (int)(1.0f + e) + 2;

    // Word-parallel candidate test (R16): no false negatives for T < 120;
    // borrow-induced false positives filtered by the exact per-byte re-check.
    const bool fast = (T < 120);
    const uint32_t Nb = (uint32_t)(min(T, 119) + 129) * 0x01010101u;

    #pragma unroll
    for (int i = 0; i < 4; i++) {
        const int pb = (t + i * 128) * 16;
        const uint32_t uu[4] = { (uint32_t)v[i].x, (uint32_t)v[i].y,
                                 (uint32_t)v[i].z, (uint32_t)v[i].w };
        #pragma unroll
        for (int j = 0; j < 4; j++) {
            const uint32_t u = uu[j];
            const uint32_t x = u ^ 0x80808080u;
            const uint32_t m = fast ? ((x - Nb) & ~x & 0x80808080u) : 0x80808080u;
            if (m) {
                #pragma unroll
                for (int byi = 0; byi < 4; byi++) {
                    int q = sx8(u, byi);
                    if (q <= T) {
                        int pos = pb + j * 4 + byi;
                        int k = (pos & ~63) | (((pos >> 1) & 7) << 3) |
                                (((pos >> 4) & 3) << 1) | (pos & 1);
                        int slot = atomicAdd(&ccnt, 1);
                        if (slot < 128) candk[slot] = k; else covf = 1;
                    }
                }
            }
        }
    }
    __syncthreads();

    const int cnt = min(ccnt, 128);
    if (!covf && cnt > 0) {
        const float4* z4p = reinterpret_cast<const float4*>(zrow);
        for (int s = w; s < cnt; s += 4) {
            const int k = candk[s];
            const float4 c4 = __ldg(reinterpret_cast<const float4*>(cb + (size_t)k * DDIM) + lane);
            const float4 z4 = z4p[lane];
            float d = c4.x * z4.x + c4.y * z4.y + c4.z * z4.z + c4.w * z4.w;
            #pragma unroll
            for (int off = 16; off > 0; off >>= 1) d += __shfl_xor_sync(0xffffffffu, d, off);
            if (lane == 0) cdist[s] = __ldg(g_cnorm + k) - 2.0f * d;
        }
        __syncthreads();
        if (t == 0) {
            float bv = cdist[0]; int bi = candk[0];
            for (int s = 1; s < cnt; s++) {
                float dv = cdist[s]; int kv = candk[s];
                if (dv < bv || (dv == bv && kv < bi)) { bv = dv; bi = kv; }
            }
            bidx_s = bi;
        }
    } else {
        float bv = 3.402823466e38f; int bi = 0x7fffffff;
        for (int k = t; k < KCODES; k += 128) {
            float d = 0.0f;
            #pragma unroll 8
            for (int dd = 0; dd < DDIM; dd++) d += zrow[dd] * __ldg(cb + (size_t)k * DDIM + dd);
            float dist = __ldg(g_cnorm + k) - 2.0f * d;
            if (dist < bv || (dist == bv && k < bi)) { bv = dist; bi = k; }
        }
        #pragma unroll
        for (int off = 16; off > 0; off >>= 1) {
            float ov = __shfl_xor_sync(0xffffffffu, bv, off);
            int   oi = __shfl_xor_sync(0xffffffffu, bi, off);
            if (ov < bv || (ov == bv && oi < bi)) { bv = ov; bi = oi; }
        }
        if (lane == 0) { cdist[w] = bv; candk[w] = bi; }
        __syncthreads();
        if (t == 0) {
            float fv = cdist[0]; int fi = candk[0];
            for (int s = 1; s < 4; s++)
                if (cdist[s] < fv || (cdist[s] == fv && candk[s] < fi)) { fv = cdist[s]; fi = candk[s]; }
            bidx_s = fi;
        }
    }
    __syncthreads();

    const int bi = bidx_s;
    atomicAdd(&g_dw[(size_t)bi * DDIM + t], zrow[t]);
    if (t == 0) {
        atomicAdd(&g_counts[bi], 1.0f);
        g_idx[n] = bi;
        out[O_IDX + n] = (float)bi;
    }
}

// ---------------------------------------------------------------- finalize
__global__ void finalize_kernel(const float* __restrict__ ema_count,
                                const float* __restrict__ ema_weight,
                                float* __restrict__ out) {
    int k = blockIdx.x, d = threadIdx.x;
    float cnt = ema_count[k] * 0.99f + 0.01f * g_counts[k];
    float w = ema_weight[(size_t)k * DDIM + d] * 0.99f + 0.01f * g_dw[(size_t)k * DDIM + d];
    out[O_WT + (size_t)k * DDIM + d] = w;
    out[O_CB + (size_t)k * DDIM + d] = w / fmaxf(cnt, 1.0f);
    if (d == 0) out[O_CNT + k] = cnt;
}

// ---------------------------------------------------------------- z_q output
__global__ void zq_kernel(const float* __restrict__ z,
                          const float* __restrict__ cb,
                          float* __restrict__ out) {
    __shared__ float q[32 * 129];
    const int n0 = blockIdx.x * 32;
    const int b = n0 >> 10, hw0 = n0 & (HWSZ - 1);
    for (int j = threadIdx.x; j < 32 * 128; j += 256) {
        int p = j >> 7, d = j & 127;
        q[p * 129 + d] = cb[(size_t)g_idx[n0 + p] * DDIM + d];
    }
    __syncthreads();
    const float* zp = z + (size_t)b * DDIM * HWSZ + hw0;
    float* op = out + O_ZQ + (size_t)b * DDIM * HWSZ + hw0;
    for (int j = threadIdx.x; j < 32 * 128; j += 256) {
        int d = j >> 5, p = j & 31;
        float ze = zp[(size_t)d * HWSZ + p];
        float zq = q[p * 129 + d];
        op[(size_t)d * HWSZ + p] = ze + (zq - ze);
    }
}

// ---------------------------------------------------------------- launch
extern "C" void kernel_launch(void* const* d_in, const int* in_sizes, int n_in,
                              void* d_out, int out_size) {
    const float* z_e        = (const float*)d_in[0];
    const float* codebook   = (const float*)d_in[1];
    const float* ema_count  = (const float*)d_in[2];
    const float* ema_weight = (const float*)d_in[3];
    float* out = (float*)d_out;

    const int SMEM_DYN = MTILE * ZSTRIDE * 2 + NBUF * BUFB;  // 34816 + 55296 = 90112
    static int smem_set = 0;
    if (!smem_set) {
        cudaFuncSetAttribute(dist_kernel, cudaFuncAttributeMaxDynamicSharedMemorySize, SMEM_DYN);
        smem_set = 1;
    }

    zero_kernel<<<1, 1>>>();
    prep_cb_kernel<<<KCODES, 128>>>(codebook);
    prep_z_kernel<<<NPTS / 32, 256>>>(z_e);
    dist_kernel<<<NITEMS, 256, SMEM_DYN>>>();
    scan_kernel<<<NPTS, 128>>>(codebook, out);
    finalize_kernel<<<KCODES, 128>>>(ema_count, ema_weight, out);
    zq_kernel<<<NPTS / 32, 256>>>(z_e, codebook, out);
}